// round 15
// baseline (speedup 1.0000x reference)
#include <cuda_runtime.h>
#include <cstdint>

#define THREADS 256
#define TILE 256
#define BPS 2

__device__ unsigned int g_tile_ctr = 0u;
__device__ unsigned int g_done_ctr = 0u;

// ---------- PTX helpers ----------
__device__ __forceinline__ uint32_t smem_u32(const void* p) {
    uint32_t a;
    asm("{ .reg .u64 t; cvta.to.shared.u64 t, %1; cvt.u32.u64 %0, t; }"
        : "=r"(a) : "l"(p));
    return a;
}
__device__ __forceinline__ void mbar_init(uint32_t a, uint32_t cnt) {
    asm volatile("mbarrier.init.shared.b64 [%0], %1;" :: "r"(a), "r"(cnt) : "memory");
}
__device__ __forceinline__ void mbar_arrive_expect_tx(uint32_t a, uint32_t tx) {
    asm volatile("mbarrier.arrive.expect_tx.shared.b64 _, [%0], %1;"
                 :: "r"(a), "r"(tx) : "memory");
}
__device__ __forceinline__ void mbar_wait(uint32_t a, uint32_t phase) {
    uint32_t done;
    asm volatile("{\n\t.reg .pred p;\n\t"
        "mbarrier.try_wait.parity.acquire.cta.shared::cta.b64 p, [%1], %2;\n\t"
        "selp.b32 %0, 1, 0, p;\n\t}"
        : "=r"(done) : "r"(a), "r"(phase) : "memory");
    if (!done) {
        asm volatile("{\n\t.reg .pred P1;\n\t"
            "WLOOP%=:\n\t"
            "mbarrier.try_wait.parity.acquire.cta.shared::cta.b64 P1, [%0], %1, 0x989680;\n\t"
            "@P1 bra.uni WDONE%=;\n\t"
            "bra.uni WLOOP%=;\n\t"
            "WDONE%=:\n\t}"
            :: "r"(a), "r"(phase) : "memory");
    }
}
__device__ __forceinline__ void bulk_g2s(uint32_t sdst, const void* gsrc,
                                         uint32_t bytes, uint32_t mbar) {
    asm volatile(
        "cp.async.bulk.shared::cluster.global.mbarrier::complete_tx::bytes "
        "[%0], [%1], %2, [%3];"
        :: "r"(sdst), "l"(gsrc), "r"(bytes), "r"(mbar) : "memory");
}
__device__ __forceinline__ void bulk_s2g(void* gdst, uint32_t ssrc, uint32_t bytes) {
    asm volatile("cp.async.bulk.global.shared::cta.bulk_group [%0], [%1], %2;"
                 :: "l"(gdst), "r"(ssrc), "r"(bytes) : "memory");
}

// ---------- FK math ----------
__device__ __forceinline__ void build_R(float ex, float ey, float ez, float* R) {
    float sx, cx, sy, cy, sz, cz;
    __sincosf(ex, &sx, &cx);
    __sincosf(ey, &sy, &cy);
    __sincosf(ez, &sz, &cz);
    float sxsy = sx * sy;
    float cxsy = cx * sy;
    R[0] = cy * cz;                   R[1] = -cy * sz;                  R[2] = sy;
    R[3] = fmaf(sxsy, cz,  cx * sz);  R[4] = fmaf(-sxsy, sz, cx * cz);  R[5] = -sx * cy;
    R[6] = fmaf(-cxsy, cz, sx * sz);  R[7] = fmaf(cxsy, sz,  sx * cz);  R[8] = cx * cy;
}
__device__ __forceinline__ void chain_step(float* M, float* p,
                                           float ex, float ey, float ez, float L) {
    float R[9];
    build_R(ex, ey, ez, R);
    float T[9];
#pragma unroll
    for (int r = 0; r < 3; r++)
#pragma unroll
        for (int c = 0; c < 3; c++)
            T[3*r+c] = fmaf(M[3*r+0], R[c],
                       fmaf(M[3*r+1], R[3+c], M[3*r+2] * R[6+c]));
#pragma unroll
    for (int i = 0; i < 9; i++) M[i] = T[i];
    p[0] = fmaf(L, M[6], p[0]);
    p[1] = fmaf(L, M[7], p[1]);
    p[2] = fmaf(L, M[8], p[2]);
}
__device__ __forceinline__ void leaf_step(const float* M, const float* p,
                                          float ex, float ey, float ez, float L,
                                          float* po) {
    float R[9];
    build_R(ex, ey, ez, R);
    float r0 = fmaf(M[6], R[0], fmaf(M[7], R[3], M[8] * R[6]));
    float r1 = fmaf(M[6], R[1], fmaf(M[7], R[4], M[8] * R[7]));
    float r2 = fmaf(M[6], R[2], fmaf(M[7], R[5], M[8] * R[8]));
    po[0] = fmaf(L, r0, p[0]);
    po[1] = fmaf(L, r1, p[1]);
    po[2] = fmaf(L, r2, p[2]);
}
__device__ __forceinline__ void root_step(float* M, float* p,
                                          float ex, float ey, float ez, float L) {
    build_R(ex, ey, ez, M);
    p[0] = L * M[6]; p[1] = L * M[7]; p[2] = L * M[8];
}

// ---------- kernel ----------
__global__ void __launch_bounds__(THREADS, BPS)
fk_kernel(const float* __restrict__ euler,
          const float* __restrict__ blen,
          float* __restrict__ out, int N, int nTiles) {
    // 2 dual-use buffers (TILE=256 -> 49KB TMA transfers, half the per-tile
    // overhead of TILE=128) + dynamic tile stealing with self-resetting
    // counters (single launch, replay-deterministic).
    __shared__ __align__(16) float sbuf[2][TILE * 51];
    __shared__ __align__(8) unsigned long long fullb[2];
    __shared__ int tIdx_s[2];

    int tid = threadIdx.x;

    uint32_t fb0 = smem_u32(&fullb[0]), fb1 = smem_u32(&fullb[1]);

    if (tid == 0) { mbar_init(fb0, 1); mbar_init(fb1, 1); }
    __syncthreads();

    // prologue: grab first two tiles, issue their loads
    if (tid == 0) {
#pragma unroll
        for (int j = 0; j < 2; j++) {
            int t = (int)atomicAdd(&g_tile_ctr, 1u);
            tIdx_s[j] = t;
            if (t < nTiles) {
                int base = t * TILE;
                int cnt = N - base; if (cnt > TILE) cnt = TILE;
                uint32_t fb = j ? fb1 : fb0;
                mbar_arrive_expect_tx(fb, (uint32_t)cnt * 192u);
                bulk_g2s(smem_u32(sbuf[j]), euler + (size_t)base * 48,
                         (uint32_t)cnt * 192u, fb);
            }
        }
    }
    __syncthreads();

#pragma unroll 1
    for (int it = 0; ; it++) {
        int P = it & 1;
        int t = tIdx_s[P];            // written by tid0 >=2 barriers ago
        if (t >= nTiles) break;
        uint32_t ph = (uint32_t)(it >> 1) & 1u;
        int base = t * TILE;
        int cnt = N - base; if (cnt > TILE) cnt = TILE;
        bool act = tid < cnt;
        float* bp = sbuf[P];

        // blen prefetch (global, independent of smem) before the barrier wait
        const float4* l4 = reinterpret_cast<const float4*>(blen) + (size_t)(base + tid) * 4;
        float4 Lq0, Lq1;
        if (act) { Lq0 = l4[0]; Lq1 = l4[1]; }

        mbar_wait(P ? fb1 : fb0, ph);

        // pull this thread's 48 euler floats (flat layout, 12 x LDS.128)
        float e[48];
        if (act) {
            const float4* s4 = reinterpret_cast<const float4*>(bp) + tid * 12;
#pragma unroll
            for (int q = 0; q < 12; q++) {
                float4 v = s4[q];
                e[4*q+0] = v.x; e[4*q+1] = v.y; e[4*q+2] = v.z; e[4*q+3] = v.w;
            }
        }
        __syncthreads();   // all euler reads done before buffer is rewritten

        if (act) {
            float4 Lq2 = l4[2], Lq3 = l4[3];
            float* slot = bp + tid * 51;
            slot[0] = 0.0f; slot[1] = 0.0f; slot[2] = 0.0f;

            float M[9], p[3], M8[9], p8[3];
#define EMIT(jj) { slot[3*(jj)] = p[0]; slot[3*(jj)+1] = p[1]; slot[3*(jj)+2] = p[2]; }
            // chain 0 -> 1 -> 2 -> 3 (joint3 = leaf)
            root_step (M, p, e[0],  e[1],  e[2],  Lq0.x); EMIT(1);
            chain_step(M, p, e[3],  e[4],  e[5],  Lq0.y); EMIT(2);
            leaf_step (M, p, e[6],  e[7],  e[8],  Lq0.z, slot + 9);
            // chain 0 -> 4 -> 5 -> 6 (joint6 = leaf)
            root_step (M, p, e[9],  e[10], e[11], Lq0.w); EMIT(4);
            chain_step(M, p, e[12], e[13], e[14], Lq1.x); EMIT(5);
            leaf_step (M, p, e[15], e[16], e[17], Lq1.y, slot + 18);
            // chain 0 -> 7 -> 8
            root_step (M, p, e[18], e[19], e[20], Lq1.z); EMIT(7);
            chain_step(M, p, e[21], e[22], e[23], Lq1.w); EMIT(8);
#pragma unroll
            for (int q = 0; q < 9; q++) M8[q] = M[q];
            p8[0] = p[0]; p8[1] = p[1]; p8[2] = p[2];
            // 8 -> 9 -> 10 (joint10 = leaf)
            chain_step(M, p, e[24], e[25], e[26], Lq2.x); EMIT(9);
            leaf_step (M, p, e[27], e[28], e[29], Lq2.y, slot + 30);
            // 8 -> 11 -> 12 -> 13 (joint13 = leaf)
#pragma unroll
            for (int q = 0; q < 9; q++) M[q] = M8[q];
            p[0] = p8[0]; p[1] = p8[1]; p[2] = p8[2];
            chain_step(M, p, e[30], e[31], e[32], Lq2.z); EMIT(11);
            chain_step(M, p, e[33], e[34], e[35], Lq2.w); EMIT(12);
            leaf_step (M, p, e[36], e[37], e[38], Lq3.x, slot + 39);
            // 8 -> 14 -> 15 -> 16 (joint16 = leaf)
#pragma unroll
            for (int q = 0; q < 9; q++) M[q] = M8[q];
            p[0] = p8[0]; p[1] = p8[1]; p[2] = p8[2];
            chain_step(M, p, e[39], e[40], e[41], Lq3.y); EMIT(14);
            chain_step(M, p, e[42], e[43], e[44], Lq3.z); EMIT(15);
            leaf_step (M, p, e[45], e[46], e[47], Lq3.w, slot + 48);
#undef EMIT
            // fallback for a non-16B-multiple tail: store directly from smem
            if (((unsigned)cnt * 204u & 15u) != 0u) {
                float* op = out + (size_t)(base + tid) * 51;
#pragma unroll
                for (int q = 0; q < 51; q++) op[q] = slot[q];
            }
        }
        __syncthreads();   // all position writes done

        if (tid == 0) {
            uint32_t obytes = (uint32_t)cnt * 204u;
            asm volatile("fence.proxy.async.shared::cta;" ::: "memory");
            if ((obytes & 15u) == 0u) {
                bulk_s2g(out + (size_t)base * 51, smem_u32(bp), obytes);
                asm volatile("cp.async.bulk.commit_group;" ::: "memory");
            }
            // steal the next tile for this buffer (used at iteration it+2)
            int t2 = (int)atomicAdd(&g_tile_ctr, 1u);
            tIdx_s[P] = t2;
            if (t2 < nTiles) {
                // reload of this buffer must wait for the store's smem reads;
                // the other buffer's tile is already resident, so this drain
                // is off the other warps' critical path.
                asm volatile("cp.async.bulk.wait_group.read 0;" ::: "memory");
                int b2 = t2 * TILE;
                int c2 = N - b2; if (c2 > TILE) c2 = TILE;
                uint32_t fb = P ? fb1 : fb0;
                mbar_arrive_expect_tx(fb, (uint32_t)c2 * 192u);
                bulk_g2s(smem_u32(bp), euler + (size_t)b2 * 48,
                         (uint32_t)c2 * 192u, fb);
            }
        }
    }

    if (tid == 0) {
        asm volatile("cp.async.bulk.wait_group 0;" ::: "memory");
        // Self-reset for the next graph replay: the LAST block to finish
        // (all stealing already done chip-wide) zeroes both counters.
        __threadfence();
        unsigned done = atomicAdd(&g_done_ctr, 1u);
        if (done == (unsigned)gridDim.x - 1u) {
            g_tile_ctr = 0u;
            g_done_ctr = 0u;
            __threadfence();
        }
    }
}

extern "C" void kernel_launch(void* const* d_in, const int* in_sizes, int n_in,
                              void* d_out, int out_size) {
    const float* euler = (const float*)d_in[0];  // (N,16,3) f32
    const float* blen  = (const float*)d_in[1];  // (N,16,1) f32
    float* out = (float*)d_out;                  // (N,17,3) f32
    int N = in_sizes[0] / 48;
    int nTiles = (N + TILE - 1) / TILE;
    int grid = 152 * BPS;                        // GB300: 152 SMs
    if (grid > nTiles) grid = nTiles;
    fk_kernel<<<grid, THREADS>>>(euler, blen, out, N, nTiles);
}

// round 16
// speedup vs baseline: 1.0008x; 1.0008x over previous
#include <cuda_runtime.h>
#include <cstdint>

#define THREADS 128
#define TILE 128
#define BPS 4

__device__ unsigned int g_tile_ctr = 0u;
__device__ unsigned int g_done_ctr = 0u;

// ---------- PTX helpers ----------
__device__ __forceinline__ uint32_t smem_u32(const void* p) {
    uint32_t a;
    asm("{ .reg .u64 t; cvta.to.shared.u64 t, %1; cvt.u32.u64 %0, t; }"
        : "=r"(a) : "l"(p));
    return a;
}
__device__ __forceinline__ void mbar_init(uint32_t a, uint32_t cnt) {
    asm volatile("mbarrier.init.shared.b64 [%0], %1;" :: "r"(a), "r"(cnt) : "memory");
}
__device__ __forceinline__ void mbar_arrive_expect_tx(uint32_t a, uint32_t tx) {
    asm volatile("mbarrier.arrive.expect_tx.shared.b64 _, [%0], %1;"
                 :: "r"(a), "r"(tx) : "memory");
}
__device__ __forceinline__ void mbar_wait(uint32_t a, uint32_t phase) {
    uint32_t done;
    asm volatile("{\n\t.reg .pred p;\n\t"
        "mbarrier.try_wait.parity.acquire.cta.shared::cta.b64 p, [%1], %2;\n\t"
        "selp.b32 %0, 1, 0, p;\n\t}"
        : "=r"(done) : "r"(a), "r"(phase) : "memory");
    if (!done) {
        asm volatile("{\n\t.reg .pred P1;\n\t"
            "WLOOP%=:\n\t"
            "mbarrier.try_wait.parity.acquire.cta.shared::cta.b64 P1, [%0], %1, 0x989680;\n\t"
            "@P1 bra.uni WDONE%=;\n\t"
            "bra.uni WLOOP%=;\n\t"
            "WDONE%=:\n\t}"
            :: "r"(a), "r"(phase) : "memory");
    }
}
__device__ __forceinline__ void bulk_g2s(uint32_t sdst, const void* gsrc,
                                         uint32_t bytes, uint32_t mbar) {
    asm volatile(
        "cp.async.bulk.shared::cluster.global.mbarrier::complete_tx::bytes "
        "[%0], [%1], %2, [%3];"
        :: "r"(sdst), "l"(gsrc), "r"(bytes), "r"(mbar) : "memory");
}
__device__ __forceinline__ void bulk_s2g(void* gdst, uint32_t ssrc, uint32_t bytes) {
    asm volatile("cp.async.bulk.global.shared::cta.bulk_group [%0], [%1], %2;"
                 :: "l"(gdst), "r"(ssrc), "r"(bytes) : "memory");
}

// ---------- FK math ----------
__device__ __forceinline__ void build_R(float ex, float ey, float ez, float* R) {
    float sx, cx, sy, cy, sz, cz;
    __sincosf(ex, &sx, &cx);
    __sincosf(ey, &sy, &cy);
    __sincosf(ez, &sz, &cz);
    float sxsy = sx * sy;
    float cxsy = cx * sy;
    R[0] = cy * cz;                   R[1] = -cy * sz;                  R[2] = sy;
    R[3] = fmaf(sxsy, cz,  cx * sz);  R[4] = fmaf(-sxsy, sz, cx * cz);  R[5] = -sx * cy;
    R[6] = fmaf(-cxsy, cz, sx * sz);  R[7] = fmaf(cxsy, sz,  sx * cz);  R[8] = cx * cy;
}
__device__ __forceinline__ void chain_step(float* M, float* p,
                                           float ex, float ey, float ez, float L) {
    float R[9];
    build_R(ex, ey, ez, R);
    float T[9];
#pragma unroll
    for (int r = 0; r < 3; r++)
#pragma unroll
        for (int c = 0; c < 3; c++)
            T[3*r+c] = fmaf(M[3*r+0], R[c],
                       fmaf(M[3*r+1], R[3+c], M[3*r+2] * R[6+c]));
#pragma unroll
    for (int i = 0; i < 9; i++) M[i] = T[i];
    p[0] = fmaf(L, M[6], p[0]);
    p[1] = fmaf(L, M[7], p[1]);
    p[2] = fmaf(L, M[8], p[2]);
}
__device__ __forceinline__ void leaf_step(const float* M, const float* p,
                                          float ex, float ey, float ez, float L,
                                          float* po) {
    float R[9];
    build_R(ex, ey, ez, R);
    float r0 = fmaf(M[6], R[0], fmaf(M[7], R[3], M[8] * R[6]));
    float r1 = fmaf(M[6], R[1], fmaf(M[7], R[4], M[8] * R[7]));
    float r2 = fmaf(M[6], R[2], fmaf(M[7], R[5], M[8] * R[8]));
    po[0] = fmaf(L, r0, p[0]);
    po[1] = fmaf(L, r1, p[1]);
    po[2] = fmaf(L, r2, p[2]);
}
__device__ __forceinline__ void root_step(float* M, float* p,
                                          float ex, float ey, float ez, float L) {
    build_R(ex, ey, ez, M);
    p[0] = L * M[6]; p[1] = L * M[7]; p[2] = L * M[8];
}

// ---------- kernel ----------
__global__ void __launch_bounds__(THREADS, BPS)
fk_kernel(const float* __restrict__ euler,
          const float* __restrict__ blen,
          float* __restrict__ out, int N, int nTiles) {
    // 2 dual-use buffers + dynamic tile stealing. The stealing counter is
    // self-resetting: the last block to finish zeroes both globals, so the
    // kernel is replay-deterministic with a SINGLE launch (no reset kernel).
    __shared__ __align__(16) float sbuf[2][TILE * 51];
    __shared__ __align__(8) unsigned long long fullb[2];
    __shared__ int tIdx_s[2];

    int tid = threadIdx.x;

    uint32_t fb0 = smem_u32(&fullb[0]), fb1 = smem_u32(&fullb[1]);

    if (tid == 0) { mbar_init(fb0, 1); mbar_init(fb1, 1); }
    __syncthreads();

    // prologue: grab first two tiles, issue their loads
    if (tid == 0) {
#pragma unroll
        for (int j = 0; j < 2; j++) {
            int t = (int)atomicAdd(&g_tile_ctr, 1u);
            tIdx_s[j] = t;
            if (t < nTiles) {
                int base = t * TILE;
                int cnt = N - base; if (cnt > TILE) cnt = TILE;
                uint32_t fb = j ? fb1 : fb0;
                mbar_arrive_expect_tx(fb, (uint32_t)cnt * 192u);
                bulk_g2s(smem_u32(sbuf[j]), euler + (size_t)base * 48,
                         (uint32_t)cnt * 192u, fb);
            }
        }
    }
    __syncthreads();

#pragma unroll 1
    for (int it = 0; ; it++) {
        int P = it & 1;
        int t = tIdx_s[P];            // written by tid0 >=2 barriers ago
        if (t >= nTiles) break;
        uint32_t ph = (uint32_t)(it >> 1) & 1u;
        int base = t * TILE;
        int cnt = N - base; if (cnt > TILE) cnt = TILE;
        bool act = tid < cnt;
        float* bp = sbuf[P];

        // blen prefetch (global, independent of smem) before the barrier wait
        const float4* l4 = reinterpret_cast<const float4*>(blen) + (size_t)(base + tid) * 4;
        float4 Lq0, Lq1;
        if (act) { Lq0 = l4[0]; Lq1 = l4[1]; }

        mbar_wait(P ? fb1 : fb0, ph);

        // pull this thread's 48 euler floats (flat layout, 12 x LDS.128)
        float e[48];
        if (act) {
            const float4* s4 = reinterpret_cast<const float4*>(bp) + tid * 12;
#pragma unroll
            for (int q = 0; q < 12; q++) {
                float4 v = s4[q];
                e[4*q+0] = v.x; e[4*q+1] = v.y; e[4*q+2] = v.z; e[4*q+3] = v.w;
            }
        }
        __syncthreads();   // all euler reads done before buffer is rewritten

        if (act) {
            float4 Lq2 = l4[2], Lq3 = l4[3];
            float* slot = bp + tid * 51;
            slot[0] = 0.0f; slot[1] = 0.0f; slot[2] = 0.0f;

            float M[9], p[3], M8[9], p8[3];
#define EMIT(jj) { slot[3*(jj)] = p[0]; slot[3*(jj)+1] = p[1]; slot[3*(jj)+2] = p[2]; }
            // chain 0 -> 1 -> 2 -> 3 (joint3 = leaf)
            root_step (M, p, e[0],  e[1],  e[2],  Lq0.x); EMIT(1);
            chain_step(M, p, e[3],  e[4],  e[5],  Lq0.y); EMIT(2);
            leaf_step (M, p, e[6],  e[7],  e[8],  Lq0.z, slot + 9);
            // chain 0 -> 4 -> 5 -> 6 (joint6 = leaf)
            root_step (M, p, e[9],  e[10], e[11], Lq0.w); EMIT(4);
            chain_step(M, p, e[12], e[13], e[14], Lq1.x); EMIT(5);
            leaf_step (M, p, e[15], e[16], e[17], Lq1.y, slot + 18);
            // chain 0 -> 7 -> 8
            root_step (M, p, e[18], e[19], e[20], Lq1.z); EMIT(7);
            chain_step(M, p, e[21], e[22], e[23], Lq1.w); EMIT(8);
#pragma unroll
            for (int q = 0; q < 9; q++) M8[q] = M[q];
            p8[0] = p[0]; p8[1] = p[1]; p8[2] = p[2];
            // 8 -> 9 -> 10 (joint10 = leaf)
            chain_step(M, p, e[24], e[25], e[26], Lq2.x); EMIT(9);
            leaf_step (M, p, e[27], e[28], e[29], Lq2.y, slot + 30);
            // 8 -> 11 -> 12 -> 13 (joint13 = leaf)
#pragma unroll
            for (int q = 0; q < 9; q++) M[q] = M8[q];
            p[0] = p8[0]; p[1] = p8[1]; p[2] = p8[2];
            chain_step(M, p, e[30], e[31], e[32], Lq2.z); EMIT(11);
            chain_step(M, p, e[33], e[34], e[35], Lq2.w); EMIT(12);
            leaf_step (M, p, e[36], e[37], e[38], Lq3.x, slot + 39);
            // 8 -> 14 -> 15 -> 16 (joint16 = leaf)
#pragma unroll
            for (int q = 0; q < 9; q++) M[q] = M8[q];
            p[0] = p8[0]; p[1] = p8[1]; p[2] = p8[2];
            chain_step(M, p, e[39], e[40], e[41], Lq3.y); EMIT(14);
            chain_step(M, p, e[42], e[43], e[44], Lq3.z); EMIT(15);
            leaf_step (M, p, e[45], e[46], e[47], Lq3.w, slot + 48);
#undef EMIT
            // fallback for a non-16B-multiple tail: store directly from smem
            if (((unsigned)cnt * 204u & 15u) != 0u) {
                float* op = out + (size_t)(base + tid) * 51;
#pragma unroll
                for (int q = 0; q < 51; q++) op[q] = slot[q];
            }
        }
        __syncthreads();   // all position writes done

        if (tid == 0) {
            uint32_t obytes = (uint32_t)cnt * 204u;
            asm volatile("fence.proxy.async.shared::cta;" ::: "memory");
            if ((obytes & 15u) == 0u) {
                bulk_s2g(out + (size_t)base * 51, smem_u32(bp), obytes);
                asm volatile("cp.async.bulk.commit_group;" ::: "memory");
            }
            // steal the next tile for this buffer (used at iteration it+2)
            int t2 = (int)atomicAdd(&g_tile_ctr, 1u);
            tIdx_s[P] = t2;
            if (t2 < nTiles) {
                // reload of this buffer must wait for the store's smem reads;
                // the other buffer's tile is already resident, so this drain
                // is off the other warps' critical path.
                asm volatile("cp.async.bulk.wait_group.read 0;" ::: "memory");
                int b2 = t2 * TILE;
                int c2 = N - b2; if (c2 > TILE) c2 = TILE;
                uint32_t fb = P ? fb1 : fb0;
                mbar_arrive_expect_tx(fb, (uint32_t)c2 * 192u);
                bulk_g2s(smem_u32(bp), euler + (size_t)b2 * 48,
                         (uint32_t)c2 * 192u, fb);
            }
        }
    }

    if (tid == 0) {
        asm volatile("cp.async.bulk.wait_group 0;" ::: "memory");
        // Self-reset for the next graph replay: the LAST block to finish
        // (all stealing already done chip-wide) zeroes both counters.
        __threadfence();
        unsigned done = atomicAdd(&g_done_ctr, 1u);
        if (done == (unsigned)gridDim.x - 1u) {
            g_tile_ctr = 0u;
            g_done_ctr = 0u;
            __threadfence();
        }
    }
}

extern "C" void kernel_launch(void* const* d_in, const int* in_sizes, int n_in,
                              void* d_out, int out_size) {
    const float* euler = (const float*)d_in[0];  // (N,16,3) f32
    const float* blen  = (const float*)d_in[1];  // (N,16,1) f32
    float* out = (float*)d_out;                  // (N,17,3) f32
    int N = in_sizes[0] / 48;
    int nTiles = (N + TILE - 1) / TILE;
    int grid = 152 * BPS;                        // GB300: 152 SMs
    if (grid > nTiles) grid = nTiles;
    fk_kernel<<<grid, THREADS>>>(euler, blen, out, N, nTiles);
}